// round 6
// baseline (speedup 1.0000x reference)
#include <cuda_runtime.h>
#include <math.h>

// Image-space tiles: 4 x 8 grid of 64x32-pixel tiles. Each CTA stages one tile
// (+1 px halo => 66x34 pixels) into smem, 4 batches interleaved as one float4
// per pixel, then processes G_ANG angles. A sample (a,j,i) is owned by the tile
// containing cell (floor(px), floor(py)) — computed bit-identically in every
// CTA, so tiles partition the sample set exactly. i/j ranges are conservative
// (projection bounds, no divisions, +-2 margins); ownership filters exactly.
#define TSX 64
#define TSY 32
#define NTX 4
#define NTY 8
#define PXW (TSX + 2)   // 66
#define PXH (TSY + 2)   // 34
#define SSTR 67         // float4 row stride; 67 mod 8 = 3 -> conflict-free axis walks
#define G_ANG 6         // angles per CTA
#define NCHUNK 4        // 32-wide j chunks (max j-span ~77 < 128)
#define BLOCK 256

__global__ __launch_bounds__(256) void zero_out(float* __restrict__ out, int n) {
    int i = blockIdx.x * blockDim.x + threadIdx.x;
    if (i < n) out[i] = 0.0f;
}

__global__ __launch_bounds__(BLOCK) void radon_tiles(const float* __restrict__ x,
                                                     float* __restrict__ out) {
    __shared__ float4 tile[PXH * SSTR];   // 36448 B

    const int tid  = threadIdx.x;
    const int lane = tid & 31;
    const int warp = tid >> 5;

    const int t   = blockIdx.x;
    const int txi = t & (NTX - 1);
    const int tyi = t >> 2;
    const int GX0 = txi * TSX;
    const int GY0 = tyi * TSY;

    // Stage tile: masked image (zeros outside [0,256)^2 and outside circle).
    for (int p = tid; p < PXH * PXW; p += BLOCK) {
        int row = p / PXW;
        int col = p - row * PXW;
        int gy = GY0 - 1 + row;
        int gx = GX0 - 1 + col;
        float4 q = make_float4(0.f, 0.f, 0.f, 0.f);
        if ((unsigned)gx < 256u && (unsigned)gy < 256u) {
            int dx = gx - 128, dy = gy - 128;
            if (dx * dx + dy * dy <= 16384) {
                int o = gy * 256 + gx;
                q.x = x[o];
                q.y = x[o + 65536];
                q.z = x[o + 131072];
                q.w = x[o + 196608];
            }
        }
        tile[row * SSTR + col] = q;
    }
    __syncthreads();

    // Owned cell range (floor coords). Edge tiles also own cell -1;
    // cells <= -2 or >= 256 contribute exactly 0 and are owned by nobody.
    const int Xlo = (txi == 0) ? -1 : GX0;
    const int Xhi = GX0 + TSX - 1;
    const int Ylo = (tyi == 0) ? -1 : GY0;
    const int Yhi = GY0 + TSY - 1;
    const unsigned XR = (unsigned)(Xhi - Xlo);
    const unsigned YR = (unsigned)(Yhi - Ylo);

    // Box extents: owned samples have px in [Xlo, Xhi+1), py in [Ylo, Yhi+1)
    const float ex0 = (float)Xlo - 127.5f, ex1 = (float)(Xhi + 1) - 127.5f;
    const float ey0 = (float)Ylo - 127.5f, ey1 = (float)(Yhi + 1) - 127.5f;

    const int base = (1 - GY0) * SSTR + (1 - GX0);
    // R=131 > 130.13 = max radius of any reference-contributing sample
    // (point dist <= 128+sqrt2 from (128,128), plus rotated (0.5,0.5) offset).
    const float RR = 131.0f * 131.0f;

    for (int task = warp; task < G_ANG * NCHUNK; task += BLOCK / 32) {
        int aa = task / NCHUNK;
        int chunk = task - aa * NCHUNK;
        int a = blockIdx.y * G_ANG + aa;

        float ang = (float)a * (float)(M_PI / 179.0);
        float s, c;
        sincosf(ang, &s, &c);

        // v-range of samples in the box: v = -s*ex + c*ey
        float vlo = fminf(-s * ex0, -s * ex1) + fminf(c * ey0, c * ey1);
        float vhi = fmaxf(-s * ex0, -s * ex1) + fmaxf(c * ey0, c * ey1);
        int jlo = max(0,   (int)ceilf (vlo + 127.5f) - 2);
        int jhi = min(255, (int)floorf(vhi + 127.5f) + 2);

        int jb = jlo + chunk * 32;
        if (jb > jhi) continue;
        int j = jb + lane;
        if (j > jhi) continue;

        const float v = (float)j - 127.5f;
        // Bit-identical sample formulas to the reference-passing kernel:
        const float px0 = fmaf(-127.5f, c, fmaf(-s, v, 127.5f));
        const float py0 = fmaf(-127.5f, s, fmaf( c, v, 127.5f));

        // u-range of samples in the box: u = c*ex + s*ey (projection; no division)
        float ulo = fminf(c * ex0, c * ex1) + fminf(s * ey0, s * ey1);
        float uhi = fmaxf(c * ex0, c * ex1) + fmaxf(s * ey0, s * ey1);
        // Circle: samples with u^2+v^2 > RR have all 4 corners masked -> 0.
        float umax = sqrtf(fmaxf(RR - v * v, 0.0f));
        float lof = fmaxf(ulo + 127.5f, 127.5f - umax);
        float hif = fminf(uhi + 127.5f, 127.5f + umax);
        int ilo = max(0,   (int)floorf(lof) - 2);
        int ihi = min(255, (int)ceilf (hif) + 2);

        float acc0 = 0.f, acc1 = 0.f, acc2 = 0.f, acc3 = 0.f;

        for (int i = ilo; i <= ihi; i++) {
            float fi = (float)i;
            float px = fmaf(fi, c, px0);
            float py = fmaf(fi, s, py0);
            float fx = floorf(px);
            float fy = floorf(py);
            int x0 = (int)fx;
            int y0 = (int)fy;
            // exact ownership test: cell must be in this tile's owned range
            if ((unsigned)(x0 - Xlo) > XR) continue;
            if ((unsigned)(y0 - Ylo) > YR) continue;
            float wx = px - fx;
            float wy = py - fy;
            int idx = y0 * SSTR + x0 + base;
            float4 q00 = tile[idx];
            float4 q10 = tile[idx + 1];
            float4 q01 = tile[idx + SSTR];
            float4 q11 = tile[idx + SSTR + 1];
            float tp, bt;
            tp = fmaf(wx, q10.x - q00.x, q00.x); bt = fmaf(wx, q11.x - q01.x, q01.x);
            acc0 += fmaf(wy, bt - tp, tp);
            tp = fmaf(wx, q10.y - q00.y, q00.y); bt = fmaf(wx, q11.y - q01.y, q01.y);
            acc1 += fmaf(wy, bt - tp, tp);
            tp = fmaf(wx, q10.z - q00.z, q00.z); bt = fmaf(wx, q11.z - q01.z, q01.z);
            acc2 += fmaf(wy, bt - tp, tp);
            tp = fmaf(wx, q10.w - q00.w, q00.w); bt = fmaf(wx, q11.w - q01.w, q01.w);
            acc3 += fmaf(wy, bt - tp, tp);
        }

        if (acc0 != 0.f || acc1 != 0.f || acc2 != 0.f || acc3 != 0.f) {
            int o = a * 256 + j;
            atomicAdd(&out[o],          acc0);
            atomicAdd(&out[o +  46080], acc1);
            atomicAdd(&out[o +  92160], acc2);
            atomicAdd(&out[o + 138240], acc3);
        }
    }
}

extern "C" void kernel_launch(void* const* d_in, const int* in_sizes, int n_in,
                              void* d_out, int out_size) {
    const float* x = (const float*)d_in[0];
    float* out = (float*)d_out;

    int n = 4 * 180 * 256;
    zero_out<<<(n + 255) / 256, 256>>>(out, n);

    dim3 grid(NTX * NTY, 180 / G_ANG);   // 32 tiles x 30 angle-groups
    radon_tiles<<<grid, BLOCK>>>(x, out);
}

// round 7
// speedup vs baseline: 1.7258x; 1.7258x over previous
#include <cuda_runtime.h>
#include <cuda_fp16.h>
#include <math.h>

// Packed fp16 cell arrays. Cell (y0,x0) at index (y0+4)*PACK_W + (x0+4) holds
// the 4 bilinear corners for a batch PAIR as 4 half2:
//   .x = (qA_00, qB_00)   q00 = m[y0  ][x0  ]
//   .y = (qA_10, qB_10)   q10 = m[y0  ][x0+1]   (x-direction neighbor)
//   .z = (qA_01, qB_01)   q01 = m[y0+1][x0  ]
//   .w = (qA_11, qB_11)   q11 = m[y0+1][x0+1]
// m = circle-masked image, 0 outside [0,256)^2. Valid x0,y0 in [-4, 258].
// g_ab: batches 0,1   g_cd: batches 2,3   *_T: built on transposed image.
#define PACK_W 263
#define PACK_SZ (PACK_W * PACK_W)
__device__ uint4 g_ab [PACK_SZ];
__device__ uint4 g_cd [PACK_SZ];
__device__ uint4 g_abT[PACK_SZ];
__device__ uint4 g_cdT[PACK_SZ];

__device__ __forceinline__ unsigned h2(float a, float b) {
    __half2 h = __floats2half2_rn(a, b);
    return *reinterpret_cast<unsigned*>(&h);
}

__global__ __launch_bounds__(256) void pack_kernel(const float* __restrict__ x) {
    int idx = blockIdx.x * blockDim.x + threadIdx.x;
    if (idx >= PACK_SZ) return;
    int yy = idx / PACK_W;
    int xx = idx - yy * PACK_W;
    int y0 = yy - 4;
    int x0 = xx - 4;

    auto get = [&](int b, int yi, int xi) -> float {
        if ((unsigned)yi > 255u || (unsigned)xi > 255u) return 0.0f;
        int dx = xi - 128, dy = yi - 128;
        if (dx * dx + dy * dy > 16384) return 0.0f;   // circle mask, R=128
        return x[b * 65536 + yi * 256 + xi];
    };

    // normal orientation
    float a00 = get(0, y0, x0),     b00 = get(1, y0, x0);
    float a10 = get(0, y0, x0 + 1), b10 = get(1, y0, x0 + 1);
    float a01 = get(0, y0 + 1, x0), b01 = get(1, y0 + 1, x0);
    float a11 = get(0, y0 + 1, x0 + 1), b11 = get(1, y0 + 1, x0 + 1);
    g_ab[idx] = make_uint4(h2(a00, b00), h2(a10, b10), h2(a01, b01), h2(a11, b11));

    float c00 = get(2, y0, x0),     d00 = get(3, y0, x0);
    float c10 = get(2, y0, x0 + 1), d10 = get(3, y0, x0 + 1);
    float c01 = get(2, y0 + 1, x0), d01 = get(3, y0 + 1, x0);
    float c11 = get(2, y0 + 1, x0 + 1), d11 = get(3, y0 + 1, x0 + 1);
    g_cd[idx] = make_uint4(h2(c00, d00), h2(c10, d10), h2(c01, d01), h2(c11, d11));

    // transposed orientation: imgT[r][c] = img[c][r]
    float ta00 = get(0, x0, y0),     tb00 = get(1, x0, y0);
    float ta10 = get(0, x0 + 1, y0), tb10 = get(1, x0 + 1, y0);
    float ta01 = get(0, x0, y0 + 1), tb01 = get(1, x0, y0 + 1);
    float ta11 = get(0, x0 + 1, y0 + 1), tb11 = get(1, x0 + 1, y0 + 1);
    g_abT[idx] = make_uint4(h2(ta00, tb00), h2(ta10, tb10), h2(ta01, tb01), h2(ta11, tb11));

    float tc00 = get(2, x0, y0),     td00 = get(3, x0, y0);
    float tc10 = get(2, x0 + 1, y0), td10 = get(3, x0 + 1, y0);
    float tc01 = get(2, x0, y0 + 1), td01 = get(3, x0, y0 + 1);
    float tc11 = get(2, x0 + 1, y0 + 1), td11 = get(3, x0 + 1, y0 + 1);
    g_cdT[idx] = make_uint4(h2(tc00, td00), h2(tc10, td10), h2(tc01, td01), h2(tc11, td11));
}

__device__ __forceinline__ float2 cvt2(unsigned u) {
    __half2 h = *reinterpret_cast<__half2*>(&u);
    return __half22float2(h);
}

// One warp per ray (a, j); all 4 batches fused via two 16B cell loads.
__global__ __launch_bounds__(256) void radon_kernel(float* __restrict__ out) {
    const int a = blockIdx.y;              // angle 0..179
    const int warp = threadIdx.x >> 5;
    const int lane = threadIdx.x & 31;
    const int j = blockIdx.x * 8 + warp;   // j in [0,256)

    float ang = (float)a * (float)(M_PI / 179.0);
    float s, c;
    sincosf(ang, &s, &c);

    const float v = (float)j - 127.5f;

    // R=131 > 130.13 = max radius of any reference-contributing sample.
    const float RR = 131.0f * 131.0f;
    float umax = sqrtf(fmaxf(RR - v * v, 0.0f));
    int ilo = max(0,   (int)ceilf (127.5f - umax));
    int ihi = min(255, (int)floorf(127.5f + umax));

    // Orientation choice: walk slope |se/ce| <= 1  (bilerp(img,px,py)==bilerp(imgT,py,px))
    const bool swp = fabsf(s) > fabsf(c);
    float ce, se, px0, py0;
    if (!swp) {
        ce = c; se = s;
        px0 = fmaf(-127.5f, c, fmaf(-s, v, 127.5f));
        py0 = fmaf(-127.5f, s, fmaf( c, v, 127.5f));
    } else {
        ce = s; se = c;
        px0 = fmaf(-127.5f, s, fmaf( c, v, 127.5f));
        py0 = fmaf(-127.5f, c, fmaf(-s, v, 127.5f));
    }
    // (+4,+4) padding fold: 4*263+4 = 1056
    const uint4* __restrict__ AB = (swp ? g_abT : g_ab) + 1056;
    const uint4* __restrict__ CD = (swp ? g_cdT : g_cd) + 1056;

    float acc0 = 0.f, acc1 = 0.f, acc2 = 0.f, acc3 = 0.f;

    float fi = (float)(ilo + lane);
    for (int n = ihi - (ilo + lane); n >= 0; n -= 32, fi += 32.0f) {
        float px = fmaf(fi, ce, px0);
        float py = fmaf(fi, se, py0);
        float fx = floorf(px);
        float fy = floorf(py);
        float wx = px - fx;
        float wy = py - fy;
        int x0 = (int)fx;
        int y0 = (int)fy;
        int idx = y0 * PACK_W + x0;        // in-bounds after +1056 fold (|r|<=131)

        uint4 ab = __ldg(&AB[idx]);
        uint4 cd = __ldg(&CD[idx]);

        float2 p00 = cvt2(ab.x), p10 = cvt2(ab.y), p01 = cvt2(ab.z), p11 = cvt2(ab.w);
        float2 q00 = cvt2(cd.x), q10 = cvt2(cd.y), q01 = cvt2(cd.z), q11 = cvt2(cd.w);

        float tp, bt;
        tp = fmaf(wx, p10.x - p00.x, p00.x); bt = fmaf(wx, p11.x - p01.x, p01.x);
        acc0 += fmaf(wy, bt - tp, tp);
        tp = fmaf(wx, p10.y - p00.y, p00.y); bt = fmaf(wx, p11.y - p01.y, p01.y);
        acc1 += fmaf(wy, bt - tp, tp);
        tp = fmaf(wx, q10.x - q00.x, q00.x); bt = fmaf(wx, q11.x - q01.x, q01.x);
        acc2 += fmaf(wy, bt - tp, tp);
        tp = fmaf(wx, q10.y - q00.y, q00.y); bt = fmaf(wx, q11.y - q01.y, q01.y);
        acc3 += fmaf(wy, bt - tp, tp);
    }

    #pragma unroll
    for (int o = 16; o > 0; o >>= 1) {
        acc0 += __shfl_down_sync(0xFFFFFFFFu, acc0, o);
        acc1 += __shfl_down_sync(0xFFFFFFFFu, acc1, o);
        acc2 += __shfl_down_sync(0xFFFFFFFFu, acc2, o);
        acc3 += __shfl_down_sync(0xFFFFFFFFu, acc3, o);
    }

    if (lane == 0) {
        int o = a * 256 + j;
        out[o]          = acc0;
        out[o +  46080] = acc1;
        out[o +  92160] = acc2;
        out[o + 138240] = acc3;
    }
}

extern "C" void kernel_launch(void* const* d_in, const int* in_sizes, int n_in,
                              void* d_out, int out_size) {
    const float* x = (const float*)d_in[0];
    float* out = (float*)d_out;

    pack_kernel<<<(PACK_SZ + 255) / 256, 256>>>(x);

    dim3 grid(32, 180, 1);   // 32 j-tiles x 8 warps = 256 rays per angle
    radon_kernel<<<grid, 256>>>(out);
}

// round 8
// speedup vs baseline: 2.0891x; 1.2105x over previous
#include <cuda_runtime.h>
#include <cuda_fp16.h>
#include <math.h>

// fp16 coefficient-cell arrays with 4x2 cell blocking (one 128B line = 8 cells
// arranged 4 wide x 2 tall). Cell (cy,cx) = image cell (y0=cy-4, x0=cx-4):
//   .x = (pA00, pB00)            c0
//   .y = (pA10-pA00, pB10-pB00)  cx   (x-direction first difference, top row)
//   .z = (pA01, pB01)            c01
//   .w = (pA11-pA01, pB11-pB01)  cx2  (x-direction first difference, bottom row)
// bilerp = fma(wy, bot-top, top), top = fma(wx, cx, c0), bot = fma(wx, cx2, c01).
// m = circle-masked image (R=128, center 128), 0 outside [0,256)^2.
// g_ab: batches 0,1   g_cd: batches 2,3   *_T: transposed image.
#define PACK_DIM 264                  // multiple of 4 (x) and 2 (y)
#define PACK_SZ (PACK_DIM * PACK_DIM)
__device__ uint4 g_ab [PACK_SZ];
__device__ uint4 g_cd [PACK_SZ];
__device__ uint4 g_abT[PACK_SZ];
__device__ uint4 g_cdT[PACK_SZ];

__device__ __forceinline__ int swiz(int cy, int cx) {
    // block row stride: (264/4 blocks) * 8 cells * (2 rows) = 528 per cy-pair
    return (cy >> 1) * 528 + (cx >> 2) * 8 + ((cy & 1) << 2) + (cx & 3);
}

__device__ __forceinline__ unsigned h2(float a, float b) {
    __half2 h = __floats2half2_rn(a, b);
    return *reinterpret_cast<unsigned*>(&h);
}

__device__ __forceinline__ __half2 u2h(unsigned u) {
    return *reinterpret_cast<__half2*>(&u);
}

__global__ __launch_bounds__(256) void pack_kernel(const float* __restrict__ x) {
    int idx = blockIdx.x * blockDim.x + threadIdx.x;
    if (idx >= PACK_SZ) return;
    int cy = idx / PACK_DIM;
    int cx = idx - cy * PACK_DIM;
    int y0 = cy - 4;
    int x0 = cx - 4;

    auto get = [&](int b, int yi, int xi) -> float {
        if ((unsigned)yi > 255u || (unsigned)xi > 255u) return 0.0f;
        int dx = xi - 128, dy = yi - 128;
        if (dx * dx + dy * dy > 16384) return 0.0f;
        return x[b * 65536 + yi * 256 + xi];
    };

    float a00 = get(0, y0, x0),     b00 = get(1, y0, x0);
    float a10 = get(0, y0, x0 + 1), b10 = get(1, y0, x0 + 1);
    float a01 = get(0, y0 + 1, x0), b01 = get(1, y0 + 1, x0);
    float a11 = get(0, y0 + 1, x0 + 1), b11 = get(1, y0 + 1, x0 + 1);
    float c00 = get(2, y0, x0),     d00 = get(3, y0, x0);
    float c10 = get(2, y0, x0 + 1), d10 = get(3, y0, x0 + 1);
    float c01 = get(2, y0 + 1, x0), d01 = get(3, y0 + 1, x0);
    float c11 = get(2, y0 + 1, x0 + 1), d11 = get(3, y0 + 1, x0 + 1);

    int sn = swiz(cy, cx);
    g_ab[sn] = make_uint4(h2(a00, b00), h2(a10 - a00, b10 - b00),
                          h2(a01, b01), h2(a11 - a01, b11 - b01));
    g_cd[sn] = make_uint4(h2(c00, d00), h2(c10 - c00, d10 - d00),
                          h2(c01, d01), h2(c11 - c01, d11 - d01));

    // Transposed-image cell at (cx, cy) uses the SAME corners, permuted:
    // T00=n00, T10=n01, T01=n10, T11=n11.
    int st = swiz(cx, cy);
    g_abT[st] = make_uint4(h2(a00, b00), h2(a01 - a00, b01 - b00),
                           h2(a10, b10), h2(a11 - a10, b11 - b10));
    g_cdT[st] = make_uint4(h2(c00, d00), h2(c01 - c00, d01 - d00),
                           h2(c10, d10), h2(c11 - c10, d11 - d10));
}

// One warp per ray (a, j); all 4 batches fused via two 16B cell loads.
__global__ __launch_bounds__(256) void radon_kernel(float* __restrict__ out) {
    const int a = blockIdx.y;              // angle 0..179
    const int warp = threadIdx.x >> 5;
    const int lane = threadIdx.x & 31;
    const int j = warp * 32 + blockIdx.x;  // interleaved: balanced ray lengths per CTA

    float ang = (float)a * (float)(M_PI / 179.0);
    float s, c;
    sincosf(ang, &s, &c);

    const float v = (float)j - 127.5f;

    // R=131 > 130.13 = max radius of any reference-contributing sample.
    const float RR = 131.0f * 131.0f;
    float umax = sqrtf(fmaxf(RR - v * v, 0.0f));
    int ilo = max(0,   (int)ceilf (127.5f - umax));
    int ihi = min(255, (int)floorf(127.5f + umax));

    // Orientation choice: walk slope |se/ce| <= 1 (bilerp(img,px,py)==bilerp(imgT,py,px)).
    // Coordinates carry the +4 cell-padding fold (131.5 = 127.5 + 4), so
    // cx = floor(px4) in [0, 263] directly.
    const bool swp = fabsf(s) > fabsf(c);
    float ce, se, px0, py0;
    if (!swp) {
        ce = c; se = s;
        px0 = fmaf(-127.5f, c, fmaf(-s, v, 131.5f));
        py0 = fmaf(-127.5f, s, fmaf( c, v, 131.5f));
    } else {
        ce = s; se = c;
        px0 = fmaf(-127.5f, s, fmaf( c, v, 131.5f));
        py0 = fmaf(-127.5f, c, fmaf(-s, v, 131.5f));
    }
    const uint4* __restrict__ AB = swp ? g_abT : g_ab;
    const uint4* __restrict__ CD = swp ? g_cdT : g_cd;

    float acc0 = 0.f, acc1 = 0.f, acc2 = 0.f, acc3 = 0.f;

    float fi = (float)(ilo + lane);
    for (int n = ihi - (ilo + lane); n >= 0; n -= 32, fi += 32.0f) {
        float px = fmaf(fi, ce, px0);
        float py = fmaf(fi, se, py0);
        float fx = floorf(px);
        float fy = floorf(py);
        float wx = px - fx;
        float wy = py - fy;
        int cx = (int)fx;
        int cy = (int)fy;
        int idx = swiz(cy, cx);

        uint4 ab = __ldg(&AB[idx]);
        uint4 cd = __ldg(&CD[idx]);

        __half2 wx2 = __float2half2_rn(wx);
        __half2 wy2 = __float2half2_rn(wy);

        __half2 tA = __hfma2(wx2, u2h(ab.y), u2h(ab.x));
        __half2 bA = __hfma2(wx2, u2h(ab.w), u2h(ab.z));
        __half2 rA = __hfma2(wy2, __hsub2(bA, tA), tA);
        float2 fA = __half22float2(rA);
        acc0 += fA.x;
        acc1 += fA.y;

        __half2 tC = __hfma2(wx2, u2h(cd.y), u2h(cd.x));
        __half2 bC = __hfma2(wx2, u2h(cd.w), u2h(cd.z));
        __half2 rC = __hfma2(wy2, __hsub2(bC, tC), tC);
        float2 fC = __half22float2(rC);
        acc2 += fC.x;
        acc3 += fC.y;
    }

    #pragma unroll
    for (int o = 16; o > 0; o >>= 1) {
        acc0 += __shfl_down_sync(0xFFFFFFFFu, acc0, o);
        acc1 += __shfl_down_sync(0xFFFFFFFFu, acc1, o);
        acc2 += __shfl_down_sync(0xFFFFFFFFu, acc2, o);
        acc3 += __shfl_down_sync(0xFFFFFFFFu, acc3, o);
    }

    if (lane == 0) {
        int o = a * 256 + j;
        out[o]          = acc0;
        out[o +  46080] = acc1;
        out[o +  92160] = acc2;
        out[o + 138240] = acc3;
    }
}

extern "C" void kernel_launch(void* const* d_in, const int* in_sizes, int n_in,
                              void* d_out, int out_size) {
    const float* x = (const float*)d_in[0];
    float* out = (float*)d_out;

    pack_kernel<<<(PACK_SZ + 255) / 256, 256>>>(x);

    dim3 grid(32, 180, 1);   // 32 j-slots x 8 warps = 256 rays per angle
    radon_kernel<<<grid, 256>>>(out);
}

// round 9
// speedup vs baseline: 2.1446x; 1.0266x over previous
#include <cuda_runtime.h>
#include <cuda_fp16.h>
#include <math.h>

// fp16 coefficient-cell arrays with 4x2 cell blocking (one 128B line = 8 cells
// arranged 4 wide x 2 tall). Cell (cy,cx) = image cell (y0=cy-4, x0=cx-4):
//   .x = (pA00, pB00)            c0
//   .y = (pA10-pA00, pB10-pB00)  cx   (x first difference, top row)
//   .z = (pA01, pB01)            c01
//   .w = (pA11-pA01, pB11-pB01)  cx2  (x first difference, bottom row)
// bilerp = fma(wy, bot-top, top), top = fma(wx, cx, c0), bot = fma(wx, cx2, c01).
// m = circle-masked image (R=128, center 128), 0 outside [0,256)^2.
// g_ab: batches 0,1   g_cd: batches 2,3   *_T: transposed image.
#define PACK_DIM 264                  // multiple of 4 (x) and 2 (y)
#define PACK_SZ (PACK_DIM * PACK_DIM)
__device__ uint4 g_ab [PACK_SZ];
__device__ uint4 g_cd [PACK_SZ];
__device__ uint4 g_abT[PACK_SZ];
__device__ uint4 g_cdT[PACK_SZ];

__device__ __forceinline__ int swiz(int cy, int cx) {
    return (cy >> 1) * 528 + (cx >> 2) * 8 + ((cy & 1) << 2) + (cx & 3);
}

__device__ __forceinline__ unsigned h2(float a, float b) {
    __half2 h = __floats2half2_rn(a, b);
    return *reinterpret_cast<unsigned*>(&h);
}

__device__ __forceinline__ __half2 u2h(unsigned u) {
    return *reinterpret_cast<__half2*>(&u);
}

__global__ __launch_bounds__(256) void pack_kernel(const float* __restrict__ x) {
    int idx = blockIdx.x * blockDim.x + threadIdx.x;
    if (idx >= PACK_SZ) return;
    int cy = idx / PACK_DIM;
    int cx = idx - cy * PACK_DIM;
    int y0 = cy - 4;
    int x0 = cx - 4;

    auto get = [&](int b, int yi, int xi) -> float {
        if ((unsigned)yi > 255u || (unsigned)xi > 255u) return 0.0f;
        int dx = xi - 128, dy = yi - 128;
        if (dx * dx + dy * dy > 16384) return 0.0f;
        return x[b * 65536 + yi * 256 + xi];
    };

    float a00 = get(0, y0, x0),     b00 = get(1, y0, x0);
    float a10 = get(0, y0, x0 + 1), b10 = get(1, y0, x0 + 1);
    float a01 = get(0, y0 + 1, x0), b01 = get(1, y0 + 1, x0);
    float a11 = get(0, y0 + 1, x0 + 1), b11 = get(1, y0 + 1, x0 + 1);
    float c00 = get(2, y0, x0),     d00 = get(3, y0, x0);
    float c10 = get(2, y0, x0 + 1), d10 = get(3, y0, x0 + 1);
    float c01 = get(2, y0 + 1, x0), d01 = get(3, y0 + 1, x0);
    float c11 = get(2, y0 + 1, x0 + 1), d11 = get(3, y0 + 1, x0 + 1);

    int sn = swiz(cy, cx);
    g_ab[sn] = make_uint4(h2(a00, b00), h2(a10 - a00, b10 - b00),
                          h2(a01, b01), h2(a11 - a01, b11 - b01));
    g_cd[sn] = make_uint4(h2(c00, d00), h2(c10 - c00, d10 - d00),
                          h2(c01, d01), h2(c11 - c01, d11 - d01));

    // Transposed-image cell at (cx, cy): T00=n00, T10=n01, T01=n10, T11=n11.
    int st = swiz(cx, cy);
    g_abT[st] = make_uint4(h2(a00, b00), h2(a01 - a00, b01 - b00),
                           h2(a10, b10), h2(a11 - a10, b11 - b10));
    g_cdT[st] = make_uint4(h2(c00, d00), h2(c01 - c00, d01 - d00),
                           h2(c10, d10), h2(c11 - c10, d11 - d10));
}

// One warp per ray (a, j); all 4 batches fused via two 16B cell loads.
// Loop unrolled x2 with loads batched ahead of consumption (MLP=4).
__global__ __launch_bounds__(256) void radon_kernel(float* __restrict__ out) {
    const int a = blockIdx.y;              // angle 0..179
    const int warp = threadIdx.x >> 5;
    const int lane = threadIdx.x & 31;
    const int j = blockIdx.x * 8 + warp;   // 8 ADJACENT rays per CTA -> L1 line sharing

    float ang = (float)a * (float)(M_PI / 179.0);
    float s, c;
    sincosf(ang, &s, &c);

    const float v = (float)j - 127.5f;

    // R=131 > 130.13 = max radius of any reference-contributing sample.
    const float RR = 131.0f * 131.0f;
    float umax = sqrtf(fmaxf(RR - v * v, 0.0f));
    int ilo = max(0,   (int)ceilf (127.5f - umax));
    int ihi = min(255, (int)floorf(127.5f + umax));

    // Orientation: walk slope |se/ce| <= 1 (bilerp(img,px,py)==bilerp(imgT,py,px)).
    // 131.5 = 127.5 + 4 cell padding, so floor(px) is the padded cell index.
    const bool swp = fabsf(s) > fabsf(c);
    float ce, se, px0, py0;
    if (!swp) {
        ce = c; se = s;
        px0 = fmaf(-127.5f, c, fmaf(-s, v, 131.5f));
        py0 = fmaf(-127.5f, s, fmaf( c, v, 131.5f));
    } else {
        ce = s; se = c;
        px0 = fmaf(-127.5f, s, fmaf( c, v, 131.5f));
        py0 = fmaf(-127.5f, c, fmaf(-s, v, 131.5f));
    }
    const uint4* __restrict__ AB = swp ? g_abT : g_ab;
    const uint4* __restrict__ CD = swp ? g_cdT : g_cd;

    float acc0 = 0.f, acc1 = 0.f, acc2 = 0.f, acc3 = 0.f;

    float fi = (float)(ilo + lane);
    int n = ihi - (ilo + lane);

    // main loop: two samples per lane per trip (i and i+32)
    for (; n >= 32; n -= 64, fi += 64.0f) {
        float pxA = fmaf(fi, ce, px0);
        float pyA = fmaf(fi, se, py0);
        float pxB = fmaf(fi + 32.0f, ce, px0);
        float pyB = fmaf(fi + 32.0f, se, py0);
        float fxA = floorf(pxA), fyA = floorf(pyA);
        float fxB = floorf(pxB), fyB = floorf(pyB);
        int idxA = swiz((int)fyA, (int)fxA);
        int idxB = swiz((int)fyB, (int)fxB);

        uint4 abA = __ldg(&AB[idxA]);
        uint4 cdA = __ldg(&CD[idxA]);
        uint4 abB = __ldg(&AB[idxB]);
        uint4 cdB = __ldg(&CD[idxB]);

        __half2 wxA = __float2half2_rn(pxA - fxA);
        __half2 wyA = __float2half2_rn(pyA - fyA);
        __half2 wxB = __float2half2_rn(pxB - fxB);
        __half2 wyB = __float2half2_rn(pyB - fyB);

        __half2 tA = __hfma2(wxA, u2h(abA.y), u2h(abA.x));
        __half2 bA = __hfma2(wxA, u2h(abA.w), u2h(abA.z));
        __half2 rA = __hfma2(wyA, __hsub2(bA, tA), tA);
        float2 fA = __half22float2(rA);
        __half2 tC = __hfma2(wxA, u2h(cdA.y), u2h(cdA.x));
        __half2 bC = __hfma2(wxA, u2h(cdA.w), u2h(cdA.z));
        __half2 rC = __hfma2(wyA, __hsub2(bC, tC), tC);
        float2 fC = __half22float2(rC);

        __half2 tA2 = __hfma2(wxB, u2h(abB.y), u2h(abB.x));
        __half2 bA2 = __hfma2(wxB, u2h(abB.w), u2h(abB.z));
        __half2 rA2 = __hfma2(wyB, __hsub2(bA2, tA2), tA2);
        float2 fA2 = __half22float2(rA2);
        __half2 tC2 = __hfma2(wxB, u2h(cdB.y), u2h(cdB.x));
        __half2 bC2 = __hfma2(wxB, u2h(cdB.w), u2h(cdB.z));
        __half2 rC2 = __hfma2(wyB, __hsub2(bC2, tC2), tC2);
        float2 fC2 = __half22float2(rC2);

        acc0 += fA.x + fA2.x;
        acc1 += fA.y + fA2.y;
        acc2 += fC.x + fC2.x;
        acc3 += fC.y + fC2.y;
    }

    // tail: at most one more sample
    if (n >= 0) {
        float px = fmaf(fi, ce, px0);
        float py = fmaf(fi, se, py0);
        float fx = floorf(px), fy = floorf(py);
        int idx = swiz((int)fy, (int)fx);
        uint4 ab = __ldg(&AB[idx]);
        uint4 cd = __ldg(&CD[idx]);
        __half2 wx2 = __float2half2_rn(px - fx);
        __half2 wy2 = __float2half2_rn(py - fy);
        __half2 tA = __hfma2(wx2, u2h(ab.y), u2h(ab.x));
        __half2 bA = __hfma2(wx2, u2h(ab.w), u2h(ab.z));
        __half2 rA = __hfma2(wy2, __hsub2(bA, tA), tA);
        float2 fA = __half22float2(rA);
        __half2 tC = __hfma2(wx2, u2h(cd.y), u2h(cd.x));
        __half2 bC = __hfma2(wx2, u2h(cd.w), u2h(cd.z));
        __half2 rC = __hfma2(wy2, __hsub2(bC, tC), tC);
        float2 fC = __half22float2(rC);
        acc0 += fA.x;
        acc1 += fA.y;
        acc2 += fC.x;
        acc3 += fC.y;
    }

    #pragma unroll
    for (int o = 16; o > 0; o >>= 1) {
        acc0 += __shfl_down_sync(0xFFFFFFFFu, acc0, o);
        acc1 += __shfl_down_sync(0xFFFFFFFFu, acc1, o);
        acc2 += __shfl_down_sync(0xFFFFFFFFu, acc2, o);
        acc3 += __shfl_down_sync(0xFFFFFFFFu, acc3, o);
    }

    if (lane == 0) {
        int o = a * 256 + j;
        out[o]          = acc0;
        out[o +  46080] = acc1;
        out[o +  92160] = acc2;
        out[o + 138240] = acc3;
    }
}

extern "C" void kernel_launch(void* const* d_in, const int* in_sizes, int n_in,
                              void* d_out, int out_size) {
    const float* x = (const float*)d_in[0];
    float* out = (float*)d_out;

    pack_kernel<<<(PACK_SZ + 255) / 256, 256>>>(x);

    dim3 grid(32, 180, 1);   // 32 j-tiles x 8 adjacent warps = 256 rays per angle
    radon_kernel<<<grid, 256>>>(out);
}